// round 2
// baseline (speedup 1.0000x reference)
#include <cuda_runtime.h>

#define KTAGS 48
#define PF 4
#define L2E 1.4426950408889634f
#define LN2 0.6931471805599453f

__device__ float g_res[4096];

__device__ __forceinline__ unsigned long long pk2(float lo, float hi) {
    unsigned long long r;
    asm("mov.b64 %0,{%1,%2};" : "=l"(r) : "f"(lo), "f"(hi));
    return r;
}
__device__ __forceinline__ void unpk2(unsigned long long v, float& a, float& b) {
    asm("mov.b64 {%0,%1},%2;" : "=f"(a), "=f"(b) : "l"(v));
}
__device__ __forceinline__ unsigned long long ffma2(unsigned long long a, unsigned long long b,
                                                    unsigned long long c) {
    unsigned long long d;
    asm("fma.rn.f32x2 %0,%1,%2,%3;" : "=l"(d) : "l"(a), "l"(b), "l"(c));
    return d;
}
__device__ __forceinline__ unsigned long long fadd2(unsigned long long a, unsigned long long b) {
    unsigned long long d;
    asm("add.rn.f32x2 %0,%1,%2;" : "=l"(d) : "l"(a), "l"(b));
    return d;
}
__device__ __forceinline__ float ex2f(float x) {
    float r; asm("ex2.approx.f32 %0,%1;" : "=f"(r) : "f"(x)); return r;
}
__device__ __forceinline__ float lg2f(float x) {
    float r; asm("lg2.approx.f32 %0,%1;" : "=f"(r) : "f"(x)); return r;
}

// One block per batch element. 48 threads; thread i owns output tag i.
// Recursion in linear domain with a one-step-stale shift M (= alpha_0 of the
// previous step): each timestep = one broadcast-LDS matvec (24 f32x2 FMAs),
// one EX2, one LG2, one STS, one barrier.
__global__ void __launch_bounds__(KTAGS) crf_forward(
    const float* __restrict__ emis,   // [B, T, K] f32
    const int* __restrict__ lengths,  // [B] i32
    const int* __restrict__ tags,     // [B, T] i32
    const float* __restrict__ prior,  // [K]
    const float* __restrict__ trans,  // [K, K]  trans[i*K+j] = score(j -> i)
    const float* __restrict__ ftrans, // [K]
    int T)
{
    __shared__ __align__(16) float sv[2][KTAGS];  // v buffers (double-buffered)
    __shared__ float shA[2];                      // alpha_0 of the step that wrote each buffer
    __shared__ float red[KTAGS];

    const int b = blockIdx.x;
    const int i = threadIdx.x;

    int L = lengths[b];
    if (L < 1) L = 1;
    if (L > T) L = T;

    const float* eb = emis + (size_t)b * T * KTAGS;

    // Row i of E = exp(transition[i, :]) packed as 24 f32x2 registers.
    unsigned long long E[24];
    {
        const float4* tr = (const float4*)(trans + i * KTAGS);
#pragma unroll
        for (int q = 0; q < 12; q++) {
            float4 v = tr[q];
            E[2 * q]     = pk2(ex2f(v.x * L2E), ex2f(v.y * L2E));
            E[2 * q + 1] = pk2(ex2f(v.z * L2E), ex2f(v.w * L2E));
        }
    }

    // t = 0
    float alpha = eb[i] + prior[i];
    if (i == 0) shA[0] = alpha;
    __syncthreads();
    float Mp = shA[0];                       // scale of buffer 0
    sv[0][i] = ex2f((alpha - Mp) * L2E);
    __syncthreads();
    int p = 0;

    // Emission prefetch ring (hide DRAM latency; step t consumes ef[0]).
    float ef[PF];
#pragma unroll
    for (int d = 0; d < PF; d++) {
        int t = 1 + d;
        ef[d] = (t < L) ? eb[(size_t)t * KTAGS + i] : 0.0f;
    }

    for (int t = 1; t < L; t++) {
        float et = ef[0];
#pragma unroll
        for (int d = 0; d < PF - 1; d++) ef[d] = ef[d + 1];
        {
            int tn = t + PF;
            ef[PF - 1] = (tn < L) ? eb[(size_t)tn * KTAGS + i] : 0.0f;
        }

        float Mq = shA[p];  // alpha_0 of previous step = scale for the buffer we write

        const ulonglong2* vv = (const ulonglong2*)sv[p];
        unsigned long long a0 = pk2(0.0f, 0.0f), a1 = a0, a2 = a0, a3 = a0;
#pragma unroll
        for (int q = 0; q < 12; q += 2) {
            ulonglong2 w0 = vv[q];
            ulonglong2 w1 = vv[q + 1];
            a0 = ffma2(E[2 * q],     w0.x, a0);
            a1 = ffma2(E[2 * q + 1], w0.y, a1);
            a2 = ffma2(E[2 * q + 2], w1.x, a2);
            a3 = ffma2(E[2 * q + 3], w1.y, a3);
        }
        unsigned long long s2 = fadd2(fadd2(a0, a1), fadd2(a2, a3));
        float slo, shi;
        unpk2(s2, slo, shi);
        float s = slo + shi;

        alpha = lg2f(s) * LN2 + Mp + et;

        int q = p ^ 1;
        sv[q][i] = ex2f((alpha - Mq) * L2E);
        if (i == 0) shA[q] = alpha;
        __syncthreads();
        Mp = Mq;
        p = q;
    }

    // ---- logZ = logsumexp_i(alpha_i + final_transition_i) ----
    red[i] = alpha + ftrans[i];
    __syncthreads();
    float logZ = 0.0f;
    if (i == 0) {
        float m = red[0];
#pragma unroll
        for (int j = 1; j < KTAGS; j++) m = fmaxf(m, red[j]);
        float s = 0.0f;
#pragma unroll
        for (int j = 0; j < KTAGS; j++) s += ex2f((red[j] - m) * L2E);
        logZ = m + lg2f(s) * LN2;
    }
    __syncthreads();  // everyone waits before red is reused

    // ---- path score: threads stride over timesteps ----
    const int* tb = tags + (size_t)b * T;
    float acc = 0.0f;
    for (int t = i; t < L; t += KTAGS) {
        int tg = tb[t];
        tg = min(max(tg, 0), KTAGS - 1);  // defensive clamp
        float e = eb[(size_t)t * KTAGS + tg];
        float tr;
        if (t == 0) {
            tr = prior[tg];
        } else {
            int tp = min(max(tb[t - 1], 0), KTAGS - 1);
            tr = trans[tg * KTAGS + tp];
        }
        acc += e + tr;
    }
    red[i] = acc;
    __syncthreads();
    if (i == 0) {
        float ps = 0.0f;
#pragma unroll
        for (int j = 0; j < KTAGS; j++) ps += red[j];
        int ft = min(max(tb[L - 1], 0), KTAGS - 1);
        ps += ftrans[ft];
        g_res[b] = logZ - ps;
    }
}

__global__ void crf_reduce(float* __restrict__ out, int B) {
    __shared__ float sh[512];
    int i = threadIdx.x;
    float v = 0.0f;
    for (int j = i; j < B; j += 512) v += g_res[j];
    sh[i] = v;
    __syncthreads();
#pragma unroll
    for (int s = 256; s > 0; s >>= 1) {
        if (i < s) sh[i] += sh[i + s];
        __syncthreads();
    }
    if (i == 0) out[0] = sh[0] / (float)B;
}

extern "C" void kernel_launch(void* const* d_in, const int* in_sizes, int n_in,
                              void* d_out, int out_size) {
    const float* emis    = (const float*)d_in[0];
    const int*   lengths = (const int*)d_in[1];
    const int*   tags    = (const int*)d_in[2];
    const float* prior   = (const float*)d_in[3];
    const float* trans   = (const float*)d_in[4];
    const float* ftrans  = (const float*)d_in[5];

    const int B = in_sizes[1];              // lengths count
    const int T = in_sizes[2] / B;          // tags = [B, T]

    crf_forward<<<B, KTAGS>>>(emis, lengths, tags, prior, trans, ftrans, T);
    crf_reduce<<<1, 512>>>((float*)d_out, B);
}

// round 3
// speedup vs baseline: 1.0931x; 1.0931x over previous
#include <cuda_runtime.h>

#define KTAGS 48
#define PF 4
#define L2E 1.4426950408889634f
#define LN2 0.6931471805599453f

__device__ float g_res[4096];

__device__ __forceinline__ unsigned long long pk2(float lo, float hi) {
    unsigned long long r;
    asm("mov.b64 %0,{%1,%2};" : "=l"(r) : "f"(lo), "f"(hi));
    return r;
}
__device__ __forceinline__ void unpk2(unsigned long long v, float& a, float& b) {
    asm("mov.b64 {%0,%1},%2;" : "=f"(a), "=f"(b) : "l"(v));
}
__device__ __forceinline__ unsigned long long ffma2(unsigned long long a, unsigned long long b,
                                                    unsigned long long c) {
    unsigned long long d;
    asm("fma.rn.f32x2 %0,%1,%2,%3;" : "=l"(d) : "l"(a), "l"(b), "l"(c));
    return d;
}
__device__ __forceinline__ unsigned long long fadd2(unsigned long long a, unsigned long long b) {
    unsigned long long d;
    asm("add.rn.f32x2 %0,%1,%2;" : "=l"(d) : "l"(a), "l"(b));
    return d;
}
__device__ __forceinline__ float ex2f(float x) {
    float r; asm("ex2.approx.f32 %0,%1;" : "=f"(r) : "f"(x)); return r;
}
__device__ __forceinline__ float lg2f(float x) {
    float r; asm("lg2.approx.f32 %0,%1;" : "=f"(r) : "f"(x)); return r;
}
__device__ __forceinline__ float rcpf(float x) {
    float r; asm("rcp.approx.f32 %0,%1;" : "=f"(r) : "f"(x)); return r;
}

// One block per batch element; thread i owns tag-row i.
// Linear-domain recursion: w(t) = (E w(t-1)) * exp(emis_t) / r,  r = w0(t-1).
// Log scale tracked off the critical path: C2 += lg2(r).
// Per-step critical chain: bar -> LDS -> FFMA2 tree -> 1 FMUL -> STS.
// No EX2/LG2/RCP on the chain (prefetched / parallel).
__global__ void __launch_bounds__(KTAGS) crf_forward(
    const float* __restrict__ emis,   // [B, T, K] f32
    const int* __restrict__ lengths,  // [B] i32
    const int* __restrict__ tags,     // [B, T] i32
    const float* __restrict__ prior,  // [K]
    const float* __restrict__ trans,  // [K, K]  trans[i*K+j] = score(j -> i)
    const float* __restrict__ ftrans, // [K]
    int T)
{
    __shared__ __align__(16) float sv[2][KTAGS];  // w buffers (double-buffered)
    __shared__ float red[KTAGS];

    const int b = blockIdx.x;
    const int i = threadIdx.x;

    int L = lengths[b];
    if (L < 1) L = 1;
    if (L > T) L = T;

    const float* eb = emis + (size_t)b * T * KTAGS;

    // Row i of E = exp(transition[i, :]) packed as 24 f32x2 registers.
    unsigned long long E[24];
    {
        const float4* tr = (const float4*)(trans + i * KTAGS);
#pragma unroll
        for (int q = 0; q < 12; q++) {
            float4 v = tr[q];
            E[2 * q]     = pk2(ex2f(v.x * L2E), ex2f(v.y * L2E));
            E[2 * q + 1] = pk2(ex2f(v.z * L2E), ex2f(v.w * L2E));
        }
    }

    // t = 0: alpha0_i = emis0_i + prior_i; normalize by alpha0_0.
    float a0 = eb[i] + prior[i];
    red[i] = a0;
    __syncthreads();
    float m = red[0];
    float C2 = m * L2E;                  // running log2-scale: alpha_i = ln(w_i) + LN2*C2
    float w = ex2f((a0 - m) * L2E);
    sv[0][i] = w;
    __syncthreads();
    int p = 0;

    // Prefetch ring of PRE-EXPONENTIATED emissions (MUFU hidden, PF steps ahead).
    float ef[PF];
#pragma unroll
    for (int d = 0; d < PF; d++) {
        int t = 1 + d;
        ef[d] = (t < L) ? ex2f(eb[(size_t)t * KTAGS + i] * L2E) : 1.0f;
    }

    for (int t = 1; t < L; t++) {
        float eet = ef[0];
#pragma unroll
        for (int d = 0; d < PF - 1; d++) ef[d] = ef[d + 1];
        {
            int tn = t + PF;
            ef[PF - 1] = (tn < L) ? ex2f(eb[(size_t)tn * KTAGS + i] * L2E) : 1.0f;
        }

        // Stale renormalizer: issues first; RCP runs parallel to the FFMA tree.
        float r = sv[p][0];
        float g = eet * rcpf(r);        // per-row gain, ready before u
        C2 += lg2f(r);                   // off-chain scale accumulation

        const ulonglong2* vv = (const ulonglong2*)sv[p];
        unsigned long long acc0 = pk2(0.0f, 0.0f), acc1 = acc0, acc2 = acc0, acc3 = acc0;
#pragma unroll
        for (int q = 0; q < 12; q += 2) {
            ulonglong2 w0 = vv[q];
            ulonglong2 w1 = vv[q + 1];
            acc0 = ffma2(E[2 * q],     w0.x, acc0);
            acc1 = ffma2(E[2 * q + 1], w0.y, acc1);
            acc2 = ffma2(E[2 * q + 2], w1.x, acc2);
            acc3 = ffma2(E[2 * q + 3], w1.y, acc3);
        }
        unsigned long long s2 = fadd2(fadd2(acc0, acc1), fadd2(acc2, acc3));
        float slo, shi;
        unpk2(s2, slo, shi);
        w = (slo + shi) * g;             // single FMUL on the chain

        int q = p ^ 1;
        sv[q][i] = w;
        __syncthreads();
        p = q;
    }

    // ---- logZ = LN2 * (C2 + lg2(sum_i w_i * exp(ftrans_i))) ----
    red[i] = w * ex2f(ftrans[i] * L2E);
    __syncthreads();
    float logZ = 0.0f;
    if (i == 0) {
        float s = 0.0f;
#pragma unroll
        for (int j = 0; j < KTAGS; j++) s += red[j];
        logZ = (lg2f(s) + C2) * LN2;
    }
    __syncthreads();  // red reused below

    // ---- path score: threads stride over timesteps ----
    const int* tb = tags + (size_t)b * T;
    float acc = 0.0f;
    for (int t = i; t < L; t += KTAGS) {
        int tg = min(max(tb[t], 0), KTAGS - 1);
        float e = eb[(size_t)t * KTAGS + tg];
        float tr;
        if (t == 0) {
            tr = prior[tg];
        } else {
            int tp = min(max(tb[t - 1], 0), KTAGS - 1);
            tr = trans[tg * KTAGS + tp];
        }
        acc += e + tr;
    }
    red[i] = acc;
    __syncthreads();
    if (i == 0) {
        float ps = 0.0f;
#pragma unroll
        for (int j = 0; j < KTAGS; j++) ps += red[j];
        int ft = min(max(tb[L - 1], 0), KTAGS - 1);
        ps += ftrans[ft];
        g_res[b] = logZ - ps;
    }
}

__global__ void crf_reduce(float* __restrict__ out, int B) {
    __shared__ float sh[512];
    int i = threadIdx.x;
    float v = 0.0f;
    for (int j = i; j < B; j += 512) v += g_res[j];
    sh[i] = v;
    __syncthreads();
#pragma unroll
    for (int s = 256; s > 0; s >>= 1) {
        if (i < s) sh[i] += sh[i + s];
        __syncthreads();
    }
    if (i == 0) out[0] = sh[0] / (float)B;
}

extern "C" void kernel_launch(void* const* d_in, const int* in_sizes, int n_in,
                              void* d_out, int out_size) {
    const float* emis    = (const float*)d_in[0];
    const int*   lengths = (const int*)d_in[1];
    const int*   tags    = (const int*)d_in[2];
    const float* prior   = (const float*)d_in[3];
    const float* trans   = (const float*)d_in[4];
    const float* ftrans  = (const float*)d_in[5];

    const int B = in_sizes[1];              // lengths count
    const int T = in_sizes[2] / B;          // tags = [B, T]

    crf_forward<<<B, KTAGS>>>(emis, lengths, tags, prior, trans, ftrans, T);
    crf_reduce<<<1, 512>>>((float*)d_out, B);
}

// round 4
// speedup vs baseline: 1.2396x; 1.1340x over previous
#include <cuda_runtime.h>

#define KTAGS 48
#define PF 16
#define L2E 1.4426950408889634f
#define LN2 0.6931471805599453f

__device__ float g_res[4096];

__device__ __forceinline__ unsigned long long pk2(float lo, float hi) {
    unsigned long long r;
    asm("mov.b64 %0,{%1,%2};" : "=l"(r) : "f"(lo), "f"(hi));
    return r;
}
__device__ __forceinline__ void unpk2(unsigned long long v, float& a, float& b) {
    asm("mov.b64 {%0,%1},%2;" : "=f"(a), "=f"(b) : "l"(v));
}
__device__ __forceinline__ unsigned long long ffma2(unsigned long long a, unsigned long long b,
                                                    unsigned long long c) {
    unsigned long long d;
    asm("fma.rn.f32x2 %0,%1,%2,%3;" : "=l"(d) : "l"(a), "l"(b), "l"(c));
    return d;
}
__device__ __forceinline__ unsigned long long fadd2(unsigned long long a, unsigned long long b) {
    unsigned long long d;
    asm("add.rn.f32x2 %0,%1,%2;" : "=l"(d) : "l"(a), "l"(b));
    return d;
}
__device__ __forceinline__ float ex2f(float x) {
    float r; asm("ex2.approx.f32 %0,%1;" : "=f"(r) : "f"(x)); return r;
}
__device__ __forceinline__ float lg2f(float x) {
    float r; asm("lg2.approx.f32 %0,%1;" : "=f"(r) : "f"(x)); return r;
}
__device__ __forceinline__ float rcpf(float x) {
    float r; asm("rcp.approx.f32 %0,%1;" : "=f"(r) : "f"(x)); return r;
}

// One block per batch element; thread i owns tag-row i.
// Linear-domain recursion: w(t) = (E w(t-1)) * exp(emis_t) / r,  r = w0(t-1).
// Log scale tracked off the critical path: C2 += lg2(r).
// Emissions prefetched PF=16 steps ahead in a static-index register ring so
// DRAM latency (~600-1000 cyc) is amortized to <60 cyc/step.
__global__ void __launch_bounds__(KTAGS) crf_forward(
    const float* __restrict__ emis,   // [B, T, K] f32
    const int* __restrict__ lengths,  // [B] i32
    const int* __restrict__ tags,     // [B, T] i32
    const float* __restrict__ prior,  // [K]
    const float* __restrict__ trans,  // [K, K]  trans[i*K+j] = score(j -> i)
    const float* __restrict__ ftrans, // [K]
    int T)
{
    __shared__ __align__(16) float sv[2][KTAGS];  // w buffers (double-buffered)
    __shared__ float red[KTAGS];

    const int b = blockIdx.x;
    const int i = threadIdx.x;

    int L = lengths[b];
    if (L < 1) L = 1;
    if (L > T) L = T;

    const float* eb = emis + (size_t)b * T * KTAGS;

    // Row i of E = exp(transition[i, :]) packed as 24 f32x2 registers.
    unsigned long long E[24];
    {
        const float4* tr = (const float4*)(trans + i * KTAGS);
#pragma unroll
        for (int q = 0; q < 12; q++) {
            float4 v = tr[q];
            E[2 * q]     = pk2(ex2f(v.x * L2E), ex2f(v.y * L2E));
            E[2 * q + 1] = pk2(ex2f(v.z * L2E), ex2f(v.w * L2E));
        }
    }

    // Deep prefetch ring of RAW emissions (exp applied at consume time).
    float raw[PF];
#pragma unroll
    for (int d = 0; d < PF; d++) {
        int t = 1 + d;
        raw[d] = (t < L) ? eb[(size_t)t * KTAGS + i] : 0.0f;
    }

    // t = 0: alpha0_i = emis0_i + prior_i; normalize by alpha0_0.
    float a0 = eb[i] + prior[i];
    red[i] = a0;
    __syncthreads();
    float m = red[0];
    float C2 = m * L2E;                  // running log2-scale: alpha_i = ln(w_i) + LN2*C2
    float w = ex2f((a0 - m) * L2E);
    sv[0][i] = w;
    __syncthreads();
    int p = 0;

    for (int t0 = 1; t0 < L; t0 += PF) {
#pragma unroll
        for (int d = 0; d < PF; d++) {
            const int t = t0 + d;
            if (t >= L) break;

            // exp(emission) for this step; raw value was loaded PF steps ago.
            float eet = ex2f(raw[d] * L2E);
            // Refill this slot PF steps ahead (predicated, stays outstanding).
            {
                int tn = t + PF;
                raw[d] = (tn < L) ? eb[(size_t)tn * KTAGS + i] : 0.0f;
            }

            // Stale renormalizer: RCP/LG2 run parallel to the FFMA tree.
            float r = sv[p][0];
            float g = eet * rcpf(r);
            C2 += lg2f(r);

            const ulonglong2* vv = (const ulonglong2*)sv[p];
            unsigned long long acc0 = pk2(0.0f, 0.0f), acc1 = acc0, acc2 = acc0, acc3 = acc0;
#pragma unroll
            for (int q = 0; q < 12; q += 2) {
                ulonglong2 w0 = vv[q];
                ulonglong2 w1 = vv[q + 1];
                acc0 = ffma2(E[2 * q],     w0.x, acc0);
                acc1 = ffma2(E[2 * q + 1], w0.y, acc1);
                acc2 = ffma2(E[2 * q + 2], w1.x, acc2);
                acc3 = ffma2(E[2 * q + 3], w1.y, acc3);
            }
            unsigned long long s2 = fadd2(fadd2(acc0, acc1), fadd2(acc2, acc3));
            float slo, shi;
            unpk2(s2, slo, shi);
            w = (slo + shi) * g;             // single FMUL on the chain

            const int q2 = p ^ 1;
            sv[q2][i] = w;
            __syncthreads();
            p = q2;
        }
    }

    // ---- logZ = LN2 * (C2 + lg2(sum_i w_i * exp(ftrans_i))) ----
    red[i] = w * ex2f(ftrans[i] * L2E);
    __syncthreads();
    float logZ = 0.0f;
    if (i == 0) {
        float s = 0.0f;
#pragma unroll
        for (int j = 0; j < KTAGS; j++) s += red[j];
        logZ = (lg2f(s) + C2) * LN2;
    }
    __syncthreads();  // red reused below

    // ---- path score: threads stride over timesteps ----
    const int* tb = tags + (size_t)b * T;
    float acc = 0.0f;
    for (int t = i; t < L; t += KTAGS) {
        int tg = min(max(tb[t], 0), KTAGS - 1);
        float e = eb[(size_t)t * KTAGS + tg];
        float tr;
        if (t == 0) {
            tr = prior[tg];
        } else {
            int tp = min(max(tb[t - 1], 0), KTAGS - 1);
            tr = trans[tg * KTAGS + tp];
        }
        acc += e + tr;
    }
    red[i] = acc;
    __syncthreads();
    if (i == 0) {
        float ps = 0.0f;
#pragma unroll
        for (int j = 0; j < KTAGS; j++) ps += red[j];
        int ft = min(max(tb[L - 1], 0), KTAGS - 1);
        ps += ftrans[ft];
        g_res[b] = logZ - ps;
    }
}

__global__ void crf_reduce(float* __restrict__ out, int B) {
    __shared__ float sh[512];
    int i = threadIdx.x;
    float v = 0.0f;
    for (int j = i; j < B; j += 512) v += g_res[j];
    sh[i] = v;
    __syncthreads();
#pragma unroll
    for (int s = 256; s > 0; s >>= 1) {
        if (i < s) sh[i] += sh[i + s];
        __syncthreads();
    }
    if (i == 0) out[0] = sh[0] / (float)B;
}

extern "C" void kernel_launch(void* const* d_in, const int* in_sizes, int n_in,
                              void* d_out, int out_size) {
    const float* emis    = (const float*)d_in[0];
    const int*   lengths = (const int*)d_in[1];
    const int*   tags    = (const int*)d_in[2];
    const float* prior   = (const float*)d_in[3];
    const float* trans   = (const float*)d_in[4];
    const float* ftrans  = (const float*)d_in[5];

    const int B = in_sizes[1];              // lengths count
    const int T = in_sizes[2] / B;          // tags = [B, T]

    crf_forward<<<B, KTAGS>>>(emis, lengths, tags, prior, trans, ftrans, T);
    crf_reduce<<<1, 512>>>((float*)d_out, B);
}